// round 1
// baseline (speedup 1.0000x reference)
#include <cuda_runtime.h>
#include <cuda_bf16.h>
#include <cstdint>

// Problem constants
#define Bsz 64
#define Tlen 1024
#define Idim 256
#define Hdim 512
#define G4H  2048          // 4*H
#define NBLK 128           // persistent scan blocks (<= SM count, 1 block/SM via smem)

// ---------------- device scratch (static: no allocation allowed) ----------------
__device__ float     g_pre[(size_t)Bsz * Tlen * G4H];   // 512 MB: pre-activations [B][T][4H]
__device__ float     g_h[2][Bsz][Hdim];                 // h double buffer
__device__ unsigned  g_count;                           // grid barrier counter

// ---------------- init: zero h[0] and barrier counter ----------------
__global__ void init_kernel() {
    int i = blockIdx.x * blockDim.x + threadIdx.x;
    if (i == 0) g_count = 0u;
    if (i < Bsz * Hdim) ((float*)g_h[0])[i] = 0.f;
}

// ---------------- Kernel A: pre = X @ W_ih^T + (b_ih + b_hh) ----------------
// C[M=65536][N=2048], K=256. 128x128 tile, BK=16, 256 threads, 8x8 microtile.
__global__ void __launch_bounds__(256) gemm_pre(const float* __restrict__ X,
                                                const float* __restrict__ W,
                                                const float* __restrict__ bih,
                                                const float* __restrict__ bhh) {
    __shared__ float As[16 * 128];   // [k][m]
    __shared__ float Ws[16 * 128];   // [k][n]
    const int m0 = blockIdx.y * 128;
    const int n0 = blockIdx.x * 128;
    const int tid = threadIdx.x;
    const int tx = tid & 15, ty = tid >> 4;

    float acc[8][8];
#pragma unroll
    for (int i = 0; i < 8; i++)
#pragma unroll
        for (int j = 0; j < 8; j++) acc[i][j] = 0.f;

    for (int kt = 0; kt < Idim; kt += 16) {
#pragma unroll
        for (int i = 0; i < 2; i++) {
            int idx = tid + i * 256;            // 0..511
            int r = idx >> 2, k4 = idx & 3;
            float4 v = __ldg((const float4*)(X + (size_t)(m0 + r) * Idim + kt) + k4);
            As[(k4 * 4 + 0) * 128 + r] = v.x;
            As[(k4 * 4 + 1) * 128 + r] = v.y;
            As[(k4 * 4 + 2) * 128 + r] = v.z;
            As[(k4 * 4 + 3) * 128 + r] = v.w;
        }
#pragma unroll
        for (int i = 0; i < 2; i++) {
            int idx = tid + i * 256;
            int r = idx >> 2, k4 = idx & 3;
            float4 v = __ldg((const float4*)(W + (size_t)(n0 + r) * Idim + kt) + k4);
            Ws[(k4 * 4 + 0) * 128 + r] = v.x;
            Ws[(k4 * 4 + 1) * 128 + r] = v.y;
            Ws[(k4 * 4 + 2) * 128 + r] = v.z;
            Ws[(k4 * 4 + 3) * 128 + r] = v.w;
        }
        __syncthreads();
#pragma unroll
        for (int k = 0; k < 16; k++) {
            float4 a0 = ((const float4*)As)[k * 32 + ty];
            float4 a1 = ((const float4*)As)[k * 32 + 16 + ty];
            float4 b0 = ((const float4*)Ws)[k * 32 + tx];
            float4 b1 = ((const float4*)Ws)[k * 32 + 16 + tx];
            float am[8] = {a0.x, a0.y, a0.z, a0.w, a1.x, a1.y, a1.z, a1.w};
            float bn[8] = {b0.x, b0.y, b0.z, b0.w, b1.x, b1.y, b1.z, b1.w};
#pragma unroll
            for (int i = 0; i < 8; i++)
#pragma unroll
                for (int j = 0; j < 8; j++) acc[i][j] += am[i] * bn[j];
        }
        __syncthreads();
    }
    // bias
    float bias[8];
#pragma unroll
    for (int j = 0; j < 8; j++) {
        int n = n0 + ((j < 4) ? (tx * 4 + j) : (64 + tx * 4 + j - 4));
        bias[j] = __ldg(bih + n) + __ldg(bhh + n);
    }
#pragma unroll
    for (int i = 0; i < 8; i++) {
        int m = m0 + ((i < 4) ? (ty * 4 + i) : (64 + ty * 4 + i - 4));
        float4 o0 = make_float4(acc[i][0] + bias[0], acc[i][1] + bias[1],
                                acc[i][2] + bias[2], acc[i][3] + bias[3]);
        float4 o1 = make_float4(acc[i][4] + bias[4], acc[i][5] + bias[5],
                                acc[i][6] + bias[6], acc[i][7] + bias[7]);
        *(float4*)(g_pre + (size_t)m * G4H + n0 + tx * 4) = o0;
        *(float4*)(g_pre + (size_t)m * G4H + n0 + 64 + tx * 4) = o1;
    }
}

// ---------------- Kernel B: persistent recurrent scan ----------------
// 128 blocks x 256 threads. Block b owns units j0..j0+3 for ALL batches.
// Thread (ju = tid>>6, b = tid&63) owns cell (b, j0+ju): c stays in a register.
// smem: w_sh[16][512] (this block's w_hh rows, loaded once),
//       h_sh[64][516] (full h, restaged per step, padded for LDS.128),
//       pre_sh[16][64], h_stage[64][4]
__global__ void __launch_bounds__(256) lstm_scan(const float* __restrict__ w_hh,
                                                 float* __restrict__ out,
                                                 float* __restrict__ hn,
                                                 float* __restrict__ cn) {
    extern __shared__ float sm[];
    float* w_sh    = sm;                         // 8192 floats
    float* h_sh    = sm + 8192;                  // 33024 floats (64 * 516)
    float* pre_sh  = sm + 8192 + 33024;          // 1024 floats
    float* h_stage = sm + 8192 + 33024 + 1024;   // 256 floats

    const int tid = threadIdx.x;
    const int ju = tid >> 6, b = tid & 63;
    const int j0 = blockIdx.x * 4;
    const int j  = j0 + ju;

    // Load this block's 16 w_hh rows (gate-major: row r -> gate r>>2, unit j0+(r&3))
#pragma unroll
    for (int i = 0; i < 8; i++) {
        int idx = tid + i * 256;                 // 0..2047 (float4 index)
        int r = idx >> 7, k4 = idx & 127;
        int grow = (r >> 2) * Hdim + j0 + (r & 3);
        ((float4*)w_sh)[r * 128 + k4] =
            __ldg((const float4*)(w_hh + (size_t)grow * Hdim) + k4);
    }

    const int pre_b = tid >> 2, pre_g = tid & 3;
    const float* pre_src = g_pre + (size_t)pre_b * Tlen * G4H + pre_g * Hdim + j0;

    const float4* w0p = (const float4*)w_sh + (0 + ju) * 128;
    const float4* w1p = (const float4*)w_sh + (4 + ju) * 128;
    const float4* w2p = (const float4*)w_sh + (8 + ju) * 128;
    const float4* w3p = (const float4*)w_sh + (12 + ju) * 128;

    float c = 0.f;

    for (int t = 0; t < Tlen; t++) {
        // stage pre slice (thread (pre_b, pre_g) loads 4 consecutive units)
        float4 pv = __ldg((const float4*)(pre_src + (size_t)t * G4H));
        pre_sh[(pre_g * 4 + 0) * 64 + pre_b] = pv.x;
        pre_sh[(pre_g * 4 + 1) * 64 + pre_b] = pv.y;
        pre_sh[(pre_g * 4 + 2) * 64 + pre_b] = pv.z;
        pre_sh[(pre_g * 4 + 3) * 64 + pre_b] = pv.w;

        // stage full h (bypass L1: other SMs wrote it last step)
        const float4* hgsrc = (const float4*)g_h[t & 1];
#pragma unroll
        for (int i = 0; i < 32; i++) {
            int idx = tid + i * 256;             // 0..8191
            int hb = idx >> 7, k4 = idx & 127;
            ((float4*)h_sh)[hb * 129 + k4] = __ldcg(hgsrc + idx);
        }
        __syncthreads();

        // 4 dot products of length 512 (2 partial chains per gate for ILP)
        float s0 = 0.f, s1 = 0.f, s2 = 0.f, s3 = 0.f;
        float u0 = 0.f, u1 = 0.f, u2 = 0.f, u3 = 0.f;
        const float4* h4 = (const float4*)h_sh + b * 129;
#pragma unroll 4
        for (int k4 = 0; k4 < 128; k4++) {
            float4 hv = h4[k4];
            float4 w0 = w0p[k4], w1 = w1p[k4], w2 = w2p[k4], w3 = w3p[k4];
            s0 += hv.x * w0.x; s0 += hv.y * w0.y; u0 += hv.z * w0.z; u0 += hv.w * w0.w;
            s1 += hv.x * w1.x; s1 += hv.y * w1.y; u1 += hv.z * w1.z; u1 += hv.w * w1.w;
            s2 += hv.x * w2.x; s2 += hv.y * w2.y; u2 += hv.z * w2.z; u2 += hv.w * w2.w;
            s3 += hv.x * w3.x; s3 += hv.y * w3.y; u3 += hv.z * w3.z; u3 += hv.w * w3.w;
        }
        float a0 = s0 + u0 + pre_sh[(0 + ju) * 64 + b];
        float a1 = s1 + u1 + pre_sh[(4 + ju) * 64 + b];
        float a2 = s2 + u2 + pre_sh[(8 + ju) * 64 + b];
        float a3 = s3 + u3 + pre_sh[(12 + ju) * 64 + b];

        float ig = 1.f / (1.f + __expf(-a0));
        float fg = 1.f / (1.f + __expf(-a1));
        float gg = tanhf(a2);
        float og = 1.f / (1.f + __expf(-a3));
        c = fg * c + ig * gg;
        float h = og * tanhf(c);

        h_stage[b * 4 + ju] = h;
        if (t == Tlen - 1) cn[(size_t)b * Hdim + j] = c;
        __syncthreads();

        if (tid < 64) {
            float4 hv4 = ((const float4*)h_stage)[tid];
            *(float4*)(out + (size_t)tid * Tlen * Hdim + (size_t)t * Hdim + j0) = hv4;
            ((float4*)g_h[(t + 1) & 1])[tid * 128 + (j0 >> 2)] = hv4;
            if (t == Tlen - 1)
                *(float4*)(hn + (size_t)tid * Hdim + j0) = hv4;
        }

        // grid barrier (release: fence+arrive; acquire: volatile spin)
        __syncthreads();
        if (tid == 0) {
            __threadfence();
            atomicAdd(&g_count, 1u);
            unsigned target = (unsigned)(t + 1) * NBLK;
            while (*((volatile unsigned*)&g_count) < target) { }
        }
        __syncthreads();
    }
}

// ---------------- launch ----------------
extern "C" void kernel_launch(void* const* d_in, const int* in_sizes, int n_in,
                              void* d_out, int out_size) {
    const float* x    = (const float*)d_in[0];
    const float* w_ih = (const float*)d_in[1];
    const float* w_hh = (const float*)d_in[2];
    const float* b_ih = (const float*)d_in[3];
    const float* b_hh = (const float*)d_in[4];

    float* out = (float*)d_out;                              // [B][T][H]
    float* hn  = out + (size_t)Bsz * Tlen * Hdim;            // [1][B][H]
    float* cn  = hn + (size_t)Bsz * Hdim;                    // [1][B][H]

    static const size_t SCAN_SMEM = (8192 + 33024 + 1024 + 256) * sizeof(float); // 169984 B
    cudaFuncSetAttribute(lstm_scan, cudaFuncAttributeMaxDynamicSharedMemorySize,
                         (int)SCAN_SMEM);

    init_kernel<<<(Bsz * Hdim + 255) / 256, 256>>>();
    gemm_pre<<<dim3(G4H / 128, (Bsz * Tlen) / 128), 256>>>(x, w_ih, b_ih, b_hh);
    lstm_scan<<<NBLK, 256, SCAN_SMEM>>>(w_hh, out, hn, cn);
}

// round 3
// speedup vs baseline: 1.7785x; 1.7785x over previous
#include <cuda_runtime.h>
#include <cuda_bf16.h>
#include <cstdint>

#define Bsz 64
#define Tlen 1024
#define Idim 256
#define Hdim 512
#define G4H  2048
#define NBLK 128

// ---------------- device scratch ----------------
__device__ float          g_pre[(size_t)Bsz * Tlen * G4H];   // [T][B][4H] (t-major for scan)
__device__ __nv_bfloat16  g_whi[G4H * Hdim];                 // w_hh split hi
__device__ __nv_bfloat16  g_wlo[G4H * Hdim];                 // w_hh split lo
__device__ __nv_bfloat16  g_hh[2][Bsz * Hdim];               // h hi, double-buffered
__device__ __nv_bfloat16  g_hl[2][Bsz * Hdim];               // h lo
__device__ unsigned       g_count;

// ---------------- mma helpers ----------------
__device__ __forceinline__ uint32_t smem_u32(const void* p) {
    uint32_t a;
    asm("{ .reg .u64 t; cvta.to.shared.u64 t, %1; cvt.u32.u64 %0, t; }" : "=r"(a) : "l"(p));
    return a;
}
__device__ __forceinline__ void ldsm4(uint32_t (&r)[4], uint32_t addr) {
    asm volatile("ldmatrix.sync.aligned.m8n8.x4.shared.b16 {%0,%1,%2,%3}, [%4];"
                 : "=r"(r[0]), "=r"(r[1]), "=r"(r[2]), "=r"(r[3]) : "r"(addr));
}
__device__ __forceinline__ void mma16816(float (&d)[4], const uint32_t (&a)[4], uint2 b) {
    asm volatile("mma.sync.aligned.m16n8k16.row.col.f32.bf16.bf16.f32 "
                 "{%0,%1,%2,%3}, {%4,%5,%6,%7}, {%8,%9}, {%0,%1,%2,%3};"
                 : "+f"(d[0]), "+f"(d[1]), "+f"(d[2]), "+f"(d[3])
                 : "r"(a[0]), "r"(a[1]), "r"(a[2]), "r"(a[3]), "r"(b.x), "r"(b.y));
}

// ---------------- prologue: split w_hh, zero h buffers, reset barrier ----------------
__global__ void prep_kernel(const float* __restrict__ w_hh) {
    int idx = blockIdx.x * blockDim.x + threadIdx.x;
    if (idx == 0) g_count = 0u;
    if (idx < 16384) {                                  // zero h split buf 0 (uint32 view)
        ((uint32_t*)g_hh[0])[idx] = 0u;
        ((uint32_t*)g_hl[0])[idx] = 0u;
    }
    if (idx < G4H * Hdim) {
        float w = w_hh[idx];
        __nv_bfloat16 hi = __float2bfloat16(w);
        float lo = w - __bfloat162float(hi);
        g_whi[idx] = hi;
        g_wlo[idx] = __float2bfloat16(lo);
    }
}

// ---------------- Kernel A: pre = X @ W_ih^T + (b_ih + b_hh), stored [t][b][4H] ----------------
__global__ void __launch_bounds__(256) gemm_pre(const float* __restrict__ X,
                                                const float* __restrict__ W,
                                                const float* __restrict__ bih,
                                                const float* __restrict__ bhh) {
    __shared__ float As[16 * 128];
    __shared__ float Ws[16 * 128];
    const int m0 = blockIdx.y * 128;
    const int n0 = blockIdx.x * 128;
    const int tid = threadIdx.x;
    const int tx = tid & 15, ty = tid >> 4;

    float acc[8][8];
#pragma unroll
    for (int i = 0; i < 8; i++)
#pragma unroll
        for (int j = 0; j < 8; j++) acc[i][j] = 0.f;

    for (int kt = 0; kt < Idim; kt += 16) {
#pragma unroll
        for (int i = 0; i < 2; i++) {
            int idx = tid + i * 256;
            int r = idx >> 2, k4 = idx & 3;
            float4 v = __ldg((const float4*)(X + (size_t)(m0 + r) * Idim + kt) + k4);
            As[(k4 * 4 + 0) * 128 + r] = v.x;
            As[(k4 * 4 + 1) * 128 + r] = v.y;
            As[(k4 * 4 + 2) * 128 + r] = v.z;
            As[(k4 * 4 + 3) * 128 + r] = v.w;
        }
#pragma unroll
        for (int i = 0; i < 2; i++) {
            int idx = tid + i * 256;
            int r = idx >> 2, k4 = idx & 3;
            float4 v = __ldg((const float4*)(W + (size_t)(n0 + r) * Idim + kt) + k4);
            Ws[(k4 * 4 + 0) * 128 + r] = v.x;
            Ws[(k4 * 4 + 1) * 128 + r] = v.y;
            Ws[(k4 * 4 + 2) * 128 + r] = v.z;
            Ws[(k4 * 4 + 3) * 128 + r] = v.w;
        }
        __syncthreads();
#pragma unroll
        for (int k = 0; k < 16; k++) {
            float4 a0 = ((const float4*)As)[k * 32 + ty];
            float4 a1 = ((const float4*)As)[k * 32 + 16 + ty];
            float4 b0 = ((const float4*)Ws)[k * 32 + tx];
            float4 b1 = ((const float4*)Ws)[k * 32 + 16 + tx];
            float am[8] = {a0.x, a0.y, a0.z, a0.w, a1.x, a1.y, a1.z, a1.w};
            float bn[8] = {b0.x, b0.y, b0.z, b0.w, b1.x, b1.y, b1.z, b1.w};
#pragma unroll
            for (int i = 0; i < 8; i++)
#pragma unroll
                for (int j = 0; j < 8; j++) acc[i][j] += am[i] * bn[j];
        }
        __syncthreads();
    }
    float bias[8];
#pragma unroll
    for (int j = 0; j < 8; j++) {
        int n = n0 + ((j < 4) ? (tx * 4 + j) : (64 + tx * 4 + j - 4));
        bias[j] = __ldg(bih + n) + __ldg(bhh + n);
    }
#pragma unroll
    for (int i = 0; i < 8; i++) {
        int mm = m0 + ((i < 4) ? (ty * 4 + i) : (64 + ty * 4 + i - 4));
        size_t drow = (size_t)(mm & (Tlen - 1)) * Bsz + (mm >> 10);   // [t][b]
        float4 o0 = make_float4(acc[i][0] + bias[0], acc[i][1] + bias[1],
                                acc[i][2] + bias[2], acc[i][3] + bias[3]);
        float4 o1 = make_float4(acc[i][4] + bias[4], acc[i][5] + bias[5],
                                acc[i][6] + bias[6], acc[i][7] + bias[7]);
        *(float4*)(g_pre + drow * G4H + n0 + tx * 4) = o0;
        *(float4*)(g_pre + drow * G4H + n0 + 64 + tx * 4) = o1;
    }
}

// ---------------- Kernel B: persistent scan with bf16-split mma.sync ----------------
// 128 blocks; block owns 4 units (j0..j0+3) -> 16 gate rows. Per step:
//   gates[64 x 16] = hhi@Whi + hhi@Wlo + hlo@Whi  (fp32 acc)
// Warps: (mt 0..3 = 16-batch tile) x (kh 0..1 = K half). K-split reduced via smem.
#define OFF_HHI   0          // 64 rows x 260 words (bf16x2 along k, padded)
#define OFF_HLO   16640
#define OFF_BFRAG 33280      // 4096 uint2: B fragments [ktg][split][n8][lane]
#define OFF_RED   41472      // 2 x 64 x 18 floats
#define OFF_PRE   43776      // 64 x 20 floats
#define OFF_HSF   45056      // 64 x 4 floats (h stage fp32)
#define OFF_HSHI  45312      // 64 x 4 bf16 (128 words)
#define OFF_HSLO  45440
#define SMEM_WORDS 45568     // 182272 bytes

__global__ void __launch_bounds__(256) lstm_scan(float* __restrict__ out,
                                                 float* __restrict__ hn,
                                                 float* __restrict__ cn) {
    extern __shared__ uint32_t smw[];
    const int tid = threadIdx.x;
    const int lane = tid & 31, wid = tid >> 5;
    const int mt = wid & 3, kh = wid >> 2;
    const int j0 = blockIdx.x * 4;

    // ---- stage B fragments once: [ktg 0..31][split][n8][lane] -> uint2 ----
    uint2* Bfrag = (uint2*)(smw + OFF_BFRAG);
    {
        const uint32_t* whi = (const uint32_t*)g_whi;   // bf16x2 view, 256 words/row
        const uint32_t* wlo = (const uint32_t*)g_wlo;
#pragma unroll
        for (int i = 0; i < 16; i++) {
            int idx = tid + i * 256;                    // 0..4095
            int l = idx & 31, n8 = (idx >> 5) & 1, sp = (idx >> 6) & 1, ktg = idx >> 7;
            int gid = l >> 2, tig = l & 3;
            int nl = n8 * 8 + gid;
            int grow = (nl >> 2) * Hdim + j0 + (nl & 3);
            int kw = ktg * 8 + tig;
            const uint32_t* src = sp ? wlo : whi;
            uint2 v;
            v.x = src[grow * 256 + kw];
            v.y = src[grow * 256 + kw + 4];
            Bfrag[idx] = v;
        }
    }

    // lane-invariant A addressing (ldmatrix x4 row pointers)
    const int mrow = mt * 16 + (lane & 7) + ((lane >> 3) & 1) * 8;
    const int halfk = (lane >> 4) & 1;
    const uint32_t a_woff = (uint32_t)(mrow * 260 + halfk * 4 + kh * 128);
    const uint32_t ahi_base = smem_u32(smw + OFF_HHI) + a_woff * 4;
    const uint32_t alo_base = smem_u32(smw + OFF_HLO) + a_woff * 4;

    float* red  = (float*)(smw + OFF_RED);
    float* prew = (float*)(smw + OFF_PRE);
    float* hsf  = (float*)(smw + OFF_HSF);
    __nv_bfloat16* hshi = (__nv_bfloat16*)(smw + OFF_HSHI);
    __nv_bfloat16* hslo = (__nv_bfloat16*)(smw + OFF_HSLO);

    const int u = tid >> 6, b = tid & 63;        // epilogue cell ownership
    const int pg = tid >> 6, pb = tid & 63;      // pre stage ownership

    float c = 0.f;

    for (int t = 0; t < Tlen; t++) {
        const int cur = t & 1, nxt = cur ^ 1;

        // ---- stage pre slice: [t][b][g*512 + j0..j0+3] ----
        {
            float4 pv = __ldg((const float4*)(g_pre + ((size_t)t * Bsz + pb) * G4H + pg * Hdim + j0));
            *(float4*)(prew + pb * 20 + pg * 4) = pv;
        }
        // ---- stage h split (64 rows x 64 uint4 each; bypass L1) ----
        {
            const uint4* shi = (const uint4*)g_hh[cur];
            const uint4* slo = (const uint4*)g_hl[cur];
#pragma unroll
            for (int i = 0; i < 16; i++) {
                int idx = tid + i * 256;             // 0..4095 uint4
                int m = idx >> 6, q = idx & 63;      // 64 uint4 per 512-bf16 row
                uint4 v = __ldcg(shi + idx);
                *(uint4*)(smw + OFF_HHI + m * 260 + q * 4) = v;
                uint4 w = __ldcg(slo + idx);
                *(uint4*)(smw + OFF_HLO + m * 260 + q * 4) = w;
            }
        }
        __syncthreads();

        // ---- MMA: D[16m x 16n] partial over this warp's K half ----
        float d[2][4] = {{0.f, 0.f, 0.f, 0.f}, {0.f, 0.f, 0.f, 0.f}};
#pragma unroll
        for (int kt = 0; kt < 16; kt++) {
            uint32_t ah[4], al[4];
            ldsm4(ah, ahi_base + kt * 32);           // 16 k-elems = 8 words = 32 bytes
            ldsm4(al, alo_base + kt * 32);
            const int ktg = kh * 16 + kt;
#pragma unroll
            for (int n8 = 0; n8 < 2; n8++) {
                uint2 bh = Bfrag[((ktg * 2 + 0) * 2 + n8) * 32 + lane];
                uint2 bl = Bfrag[((ktg * 2 + 1) * 2 + n8) * 32 + lane];
                mma16816(d[n8], ah, bh);
                mma16816(d[n8], ah, bl);
                mma16816(d[n8], al, bh);
            }
        }
        // ---- write partials to red[kh][64][18] ----
        {
            int gm = kh * 64 + mt * 16 + (lane >> 2);
            int gn = (lane & 3) * 2;
#pragma unroll
            for (int n8 = 0; n8 < 2; n8++) {
                float* p = red + gm * 18 + n8 * 8 + gn;
                p[0] = d[n8][0]; p[1] = d[n8][1];
                float* p2 = red + (gm + 8) * 18 + n8 * 8 + gn;
                p2[0] = d[n8][2]; p2[1] = d[n8][3];
            }
        }
        __syncthreads();

        // ---- epilogue: cell (b, u) ----
        {
            float a[4];
#pragma unroll
            for (int g = 0; g < 4; g++) {
                int n = g * 4 + u;
                a[g] = red[b * 18 + n] + red[(64 + b) * 18 + n] + prew[b * 20 + n];
            }
            float ig = 1.f / (1.f + __expf(-a[0]));
            float fg = 1.f / (1.f + __expf(-a[1]));
            float gg = tanhf(a[2]);
            float og = 1.f / (1.f + __expf(-a[3]));
            c = fg * c + ig * gg;
            float h = og * tanhf(c);

            hsf[b * 4 + u] = h;
            __nv_bfloat16 hi = __float2bfloat16(h);
            hshi[b * 4 + u] = hi;
            hslo[b * 4 + u] = __float2bfloat16(h - __bfloat162float(hi));
            if (t == Tlen - 1) cn[(size_t)b * Hdim + j0 + u] = c;
        }
        __syncthreads();

        // ---- writers: out + next-h split ----
        if (tid < 64) {
            float4 hv = *(float4*)(hsf + tid * 4);
            *(float4*)(out + ((size_t)tid * Tlen + t) * Hdim + j0) = hv;
            uint2 vhi = *(uint2*)(hshi + tid * 4);
            uint2 vlo = *(uint2*)(hslo + tid * 4);
            *(uint2*)(g_hh[nxt] + (size_t)tid * Hdim + j0) = vhi;
            *(uint2*)(g_hl[nxt] + (size_t)tid * Hdim + j0) = vlo;
            if (t == Tlen - 1)
                *(float4*)(hn + (size_t)tid * Hdim + j0) = hv;
        }
        __syncthreads();

        // ---- grid barrier (release fence -> arrive -> spin -> acquire fence) ----
        if (tid == 0) {
            __threadfence();
            atomicAdd(&g_count, 1u);
            unsigned target = (unsigned)(t + 1) * NBLK;
            while (*((volatile unsigned*)&g_count) < target) { }
            __threadfence();
        }
        __syncthreads();
    }
}

// ---------------- launch ----------------
extern "C" void kernel_launch(void* const* d_in, const int* in_sizes, int n_in,
                              void* d_out, int out_size) {
    const float* x    = (const float*)d_in[0];
    const float* w_ih = (const float*)d_in[1];
    const float* w_hh = (const float*)d_in[2];
    const float* b_ih = (const float*)d_in[3];
    const float* b_hh = (const float*)d_in[4];

    float* out = (float*)d_out;
    float* hn  = out + (size_t)Bsz * Tlen * Hdim;
    float* cn  = hn + (size_t)Bsz * Hdim;

    static const size_t SCAN_SMEM = SMEM_WORDS * sizeof(uint32_t);
    cudaFuncSetAttribute(lstm_scan, cudaFuncAttributeMaxDynamicSharedMemorySize,
                         (int)SCAN_SMEM);

    prep_kernel<<<4096, 256>>>(w_hh);
    gemm_pre<<<dim3(G4H / 128, (Bsz * Tlen) / 128), 256>>>(x, w_ih, b_ih, b_hh);
    lstm_scan<<<NBLK, 256, SCAN_SMEM>>>(out, hn, cn);
}

// round 4
// speedup vs baseline: 2.0099x; 1.1301x over previous
#include <cuda_runtime.h>
#include <cuda_bf16.h>
#include <cstdint>

#define Bsz 64
#define Tlen 1024
#define Idim 256
#define Hdim 512
#define G4H  2048
#define NBLK 128

// ---------------- device scratch ----------------
__device__ float          g_pre[(size_t)Bsz * Tlen * G4H];   // [T][B][4H]
__device__ __nv_bfloat16  g_whi[G4H * Hdim];                 // w_hh split
__device__ __nv_bfloat16  g_wlo[G4H * Hdim];
__device__ __nv_bfloat16  g_wihi[G4H * Idim];                // w_ih split
__device__ __nv_bfloat16  g_wilo[G4H * Idim];
__device__ __nv_bfloat16  g_xhi[(size_t)Bsz * Tlen * Idim];  // x split
__device__ __nv_bfloat16  g_xlo[(size_t)Bsz * Tlen * Idim];
__device__ __nv_bfloat16  g_hh[2][Bsz * Hdim];
__device__ __nv_bfloat16  g_hl[2][Bsz * Hdim];
__device__ unsigned       g_count;

// ---------------- mma helpers ----------------
__device__ __forceinline__ uint32_t smem_u32(const void* p) {
    uint32_t a;
    asm("{ .reg .u64 t; cvta.to.shared.u64 t, %1; cvt.u32.u64 %0, t; }" : "=r"(a) : "l"(p));
    return a;
}
__device__ __forceinline__ void ldsm4(uint32_t (&r)[4], uint32_t addr) {
    asm volatile("ldmatrix.sync.aligned.m8n8.x4.shared.b16 {%0,%1,%2,%3}, [%4];"
                 : "=r"(r[0]), "=r"(r[1]), "=r"(r[2]), "=r"(r[3]) : "r"(addr));
}
__device__ __forceinline__ void mma16816(float (&d)[4], const uint32_t (&a)[4], uint2 b) {
    asm volatile("mma.sync.aligned.m16n8k16.row.col.f32.bf16.bf16.f32 "
                 "{%0,%1,%2,%3}, {%4,%5,%6,%7}, {%8,%9}, {%0,%1,%2,%3};"
                 : "+f"(d[0]), "+f"(d[1]), "+f"(d[2]), "+f"(d[3])
                 : "r"(a[0]), "r"(a[1]), "r"(a[2]), "r"(a[3]), "r"(b.x), "r"(b.y));
}
__device__ __forceinline__ void split1(float v, __nv_bfloat16* hi, __nv_bfloat16* lo) {
    __nv_bfloat16 h = __float2bfloat16(v);
    *hi = h;
    *lo = __float2bfloat16(v - __bfloat162float(h));
}

// ---------------- prologue: split everything, zero h, reset barrier ----------------
__global__ void prep_kernel(const float* __restrict__ x,
                            const float* __restrict__ w_ih,
                            const float* __restrict__ w_hh) {
    int idx = blockIdx.x * blockDim.x + threadIdx.x;          // 0 .. 16.7M
    if (idx == 0) g_count = 0u;
    if (idx < 16384) {
        ((uint32_t*)g_hh[0])[idx] = 0u;
        ((uint32_t*)g_hl[0])[idx] = 0u;
    }
    if (idx < G4H * Hdim) split1(w_hh[idx], g_whi + idx, g_wlo + idx);
    if (idx < G4H * Idim) split1(w_ih[idx], g_wihi + idx, g_wilo + idx);
    split1(x[idx], g_xhi + idx, g_xlo + idx);                 // grid sized exactly
}

// ---------------- Kernel A: tensor-core pre-GEMM ----------------
// pre[t][b][:] = X @ W_ih^T + (b_ih+b_hh), bf16-split 3-term.
// Tile 128m x 128n, K-chunks of 64. 8 warps: wm=wid&1 (64m), wn=wid>>1 (32n).
#define GS 36                      // smem row stride in words (64 bf16 + pad)
#define TILE_W (128 * GS)          // 4608 words per split-tile
__global__ void __launch_bounds__(256) gemm_pre(const float* __restrict__ bih,
                                                const float* __restrict__ bhh) {
    extern __shared__ uint32_t sm[];
    uint32_t* xs_hi = sm;
    uint32_t* xs_lo = sm + TILE_W;
    uint32_t* ws_hi = sm + 2 * TILE_W;
    uint32_t* ws_lo = sm + 3 * TILE_W;

    const int tid = threadIdx.x;
    const int lane = tid & 31, wid = tid >> 5;
    const int wm = wid & 1, wn = wid >> 1;
    const int m0 = blockIdx.y * 128;
    const int n0 = blockIdx.x * 128;

    // ldmatrix lane decodes (word offsets)
    const uint32_t a_off = (uint32_t)(((lane & 7) + ((lane >> 3) & 1) * 8) * GS
                                      + ((lane >> 4) & 1) * 4);
    const uint32_t b_off = (uint32_t)((((lane >> 4) & 1) * 8 + (lane & 7)) * GS
                                      + ((lane >> 3) & 1) * 4);
    const uint32_t axh = smem_u32(xs_hi) + (a_off + (wm * 64) * GS) * 4;
    const uint32_t axl = smem_u32(xs_lo) + (a_off + (wm * 64) * GS) * 4;
    const uint32_t bwh = smem_u32(ws_hi) + (b_off + (wn * 32) * GS) * 4;
    const uint32_t bwl = smem_u32(ws_lo) + (b_off + (wn * 32) * GS) * 4;

    float d[4][4][4];
#pragma unroll
    for (int i = 0; i < 4; i++)
#pragma unroll
        for (int j = 0; j < 4; j++)
#pragma unroll
            for (int r = 0; r < 4; r++) d[i][j][r] = 0.f;

    for (int kc = 0; kc < Idim / 64; kc++) {
        // ---- stage 4 tiles: each 128 rows x 8 uint4 ----
#pragma unroll
        for (int i = 0; i < 4; i++) {
            int idx = tid + i * 256;                 // 0..1023
            int row = idx >> 3, q = idx & 7;
            uint32_t dst = row * GS + q * 4;
            *(uint4*)(xs_hi + dst) = *((const uint4*)(g_xhi + (size_t)(m0 + row) * Idim + kc * 64) + q);
            *(uint4*)(xs_lo + dst) = *((const uint4*)(g_xlo + (size_t)(m0 + row) * Idim + kc * 64) + q);
            *(uint4*)(ws_hi + dst) = *((const uint4*)(g_wihi + (size_t)(n0 + row) * Idim + kc * 64) + q);
            *(uint4*)(ws_lo + dst) = *((const uint4*)(g_wilo + (size_t)(n0 + row) * Idim + kc * 64) + q);
        }
        __syncthreads();

#pragma unroll
        for (int kt = 0; kt < 4; kt++) {             // 4 x k16
            uint32_t ah[4][4], al[4][4];
#pragma unroll
            for (int mi = 0; mi < 4; mi++) {
                uint32_t o = (mi * 16 * GS + kt * 8) * 4;
                ldsm4(ah[mi], axh + o);
                ldsm4(al[mi], axl + o);
            }
            uint2 bh[4], bl[4];
#pragma unroll
            for (int ni = 0; ni < 2; ni++) {
                uint32_t o = (ni * 16 * GS + kt * 8) * 4;
                uint32_t th[4], tl[4];
                ldsm4(th, bwh + o);
                ldsm4(tl, bwl + o);
                bh[ni * 2]     = make_uint2(th[0], th[1]);
                bh[ni * 2 + 1] = make_uint2(th[2], th[3]);
                bl[ni * 2]     = make_uint2(tl[0], tl[1]);
                bl[ni * 2 + 1] = make_uint2(tl[2], tl[3]);
            }
#pragma unroll
            for (int mi = 0; mi < 4; mi++)
#pragma unroll
                for (int n8 = 0; n8 < 4; n8++) {
                    mma16816(d[mi][n8], ah[mi], bh[n8]);
                    mma16816(d[mi][n8], ah[mi], bl[n8]);
                    mma16816(d[mi][n8], al[mi], bh[n8]);
                }
        }
        __syncthreads();
    }

    // ---- epilogue: bias + scatter to pre[t][b][n] ----
#pragma unroll
    for (int n8 = 0; n8 < 4; n8++) {
        int col = n0 + wn * 32 + n8 * 8 + (lane & 3) * 2;
        float bx = __ldg(bih + col) + __ldg(bhh + col);
        float by = __ldg(bih + col + 1) + __ldg(bhh + col + 1);
#pragma unroll
        for (int mi = 0; mi < 4; mi++) {
            int row0 = m0 + wm * 64 + mi * 16 + (lane >> 2);
            int row1 = row0 + 8;
            size_t dr0 = ((size_t)(row0 & (Tlen - 1)) * Bsz + (row0 >> 10)) * G4H;
            size_t dr1 = ((size_t)(row1 & (Tlen - 1)) * Bsz + (row1 >> 10)) * G4H;
            *(float2*)(g_pre + dr0 + col) = make_float2(d[mi][n8][0] + bx, d[mi][n8][1] + by);
            *(float2*)(g_pre + dr1 + col) = make_float2(d[mi][n8][2] + bx, d[mi][n8][3] + by);
        }
    }
}

// ---------------- Kernel B: persistent scan (unchanged from R3-pass) ----------------
#define OFF_HHI   0
#define OFF_HLO   16640
#define OFF_BFRAG 33280
#define OFF_RED   41472
#define OFF_PRE   43776
#define OFF_HSF   45056
#define OFF_HSHI  45312
#define OFF_HSLO  45440
#define SMEM_WORDS 45568

__global__ void __launch_bounds__(256) lstm_scan(float* __restrict__ out,
                                                 float* __restrict__ hn,
                                                 float* __restrict__ cn) {
    extern __shared__ uint32_t smw[];
    const int tid = threadIdx.x;
    const int lane = tid & 31, wid = tid >> 5;
    const int mt = wid & 3, kh = wid >> 2;
    const int j0 = blockIdx.x * 4;

    uint2* Bfrag = (uint2*)(smw + OFF_BFRAG);
    {
        const uint32_t* whi = (const uint32_t*)g_whi;
        const uint32_t* wlo = (const uint32_t*)g_wlo;
#pragma unroll
        for (int i = 0; i < 16; i++) {
            int idx = tid + i * 256;
            int l = idx & 31, n8 = (idx >> 5) & 1, sp = (idx >> 6) & 1, ktg = idx >> 7;
            int gid = l >> 2, tig = l & 3;
            int nl = n8 * 8 + gid;
            int grow = (nl >> 2) * Hdim + j0 + (nl & 3);
            int kw = ktg * 8 + tig;
            const uint32_t* src = sp ? wlo : whi;
            uint2 v;
            v.x = src[grow * 256 + kw];
            v.y = src[grow * 256 + kw + 4];
            Bfrag[idx] = v;
        }
    }

    const int mrow = mt * 16 + (lane & 7) + ((lane >> 3) & 1) * 8;
    const int halfk = (lane >> 4) & 1;
    const uint32_t a_woff = (uint32_t)(mrow * 260 + halfk * 4 + kh * 128);
    const uint32_t ahi_base = smem_u32(smw + OFF_HHI) + a_woff * 4;
    const uint32_t alo_base = smem_u32(smw + OFF_HLO) + a_woff * 4;

    float* red  = (float*)(smw + OFF_RED);
    float* prew = (float*)(smw + OFF_PRE);
    float* hsf  = (float*)(smw + OFF_HSF);
    __nv_bfloat16* hshi = (__nv_bfloat16*)(smw + OFF_HSHI);
    __nv_bfloat16* hslo = (__nv_bfloat16*)(smw + OFF_HSLO);

    const int u = tid >> 6, b = tid & 63;
    const int pg = tid >> 6, pb = tid & 63;

    float c = 0.f;

    for (int t = 0; t < Tlen; t++) {
        const int cur = t & 1, nxt = cur ^ 1;

        {
            float4 pv = __ldg((const float4*)(g_pre + ((size_t)t * Bsz + pb) * G4H + pg * Hdim + j0));
            *(float4*)(prew + pb * 20 + pg * 4) = pv;
        }
        {
            const uint4* shi = (const uint4*)g_hh[cur];
            const uint4* slo = (const uint4*)g_hl[cur];
#pragma unroll
            for (int i = 0; i < 16; i++) {
                int idx = tid + i * 256;
                int m = idx >> 6, q = idx & 63;
                uint4 v = __ldcg(shi + idx);
                *(uint4*)(smw + OFF_HHI + m * 260 + q * 4) = v;
                uint4 w = __ldcg(slo + idx);
                *(uint4*)(smw + OFF_HLO + m * 260 + q * 4) = w;
            }
        }
        __syncthreads();

        float d[2][4] = {{0.f, 0.f, 0.f, 0.f}, {0.f, 0.f, 0.f, 0.f}};
#pragma unroll
        for (int kt = 0; kt < 16; kt++) {
            uint32_t ah[4], al[4];
            ldsm4(ah, ahi_base + kt * 32);
            ldsm4(al, alo_base + kt * 32);
            const int ktg = kh * 16 + kt;
#pragma unroll
            for (int n8 = 0; n8 < 2; n8++) {
                uint2 bh = Bfrag[((ktg * 2 + 0) * 2 + n8) * 32 + lane];
                uint2 bl = Bfrag[((ktg * 2 + 1) * 2 + n8) * 32 + lane];
                mma16816(d[n8], ah, bh);
                mma16816(d[n8], ah, bl);
                mma16816(d[n8], al, bh);
            }
        }
        {
            int gm = kh * 64 + mt * 16 + (lane >> 2);
            int gn = (lane & 3) * 2;
#pragma unroll
            for (int n8 = 0; n8 < 2; n8++) {
                float* p = red + gm * 18 + n8 * 8 + gn;
                p[0] = d[n8][0]; p[1] = d[n8][1];
                float* p2 = red + (gm + 8) * 18 + n8 * 8 + gn;
                p2[0] = d[n8][2]; p2[1] = d[n8][3];
            }
        }
        __syncthreads();

        {
            float a[4];
#pragma unroll
            for (int g = 0; g < 4; g++) {
                int n = g * 4 + u;
                a[g] = red[b * 18 + n] + red[(64 + b) * 18 + n] + prew[b * 20 + n];
            }
            float ig = 1.f / (1.f + __expf(-a[0]));
            float fg = 1.f / (1.f + __expf(-a[1]));
            float gg = tanhf(a[2]);
            float og = 1.f / (1.f + __expf(-a[3]));
            c = fg * c + ig * gg;
            float h = og * tanhf(c);

            hsf[b * 4 + u] = h;
            __nv_bfloat16 hi = __float2bfloat16(h);
            hshi[b * 4 + u] = hi;
            hslo[b * 4 + u] = __float2bfloat16(h - __bfloat162float(hi));
            if (t == Tlen - 1) cn[(size_t)b * Hdim + j0 + u] = c;
        }
        __syncthreads();

        if (tid < 64) {
            float4 hv = *(float4*)(hsf + tid * 4);
            *(float4*)(out + ((size_t)tid * Tlen + t) * Hdim + j0) = hv;
            uint2 vhi = *(uint2*)(hshi + tid * 4);
            uint2 vlo = *(uint2*)(hslo + tid * 4);
            *(uint2*)(g_hh[nxt] + (size_t)tid * Hdim + j0) = vhi;
            *(uint2*)(g_hl[nxt] + (size_t)tid * Hdim + j0) = vlo;
            if (t == Tlen - 1)
                *(float4*)(hn + (size_t)tid * Hdim + j0) = hv;
        }
        __syncthreads();

        if (tid == 0) {
            __threadfence();
            atomicAdd(&g_count, 1u);
            unsigned target = (unsigned)(t + 1) * NBLK;
            while (*((volatile unsigned*)&g_count) < target) { }
            __threadfence();
        }
        __syncthreads();
    }
}

// ---------------- launch ----------------
extern "C" void kernel_launch(void* const* d_in, const int* in_sizes, int n_in,
                              void* d_out, int out_size) {
    const float* x    = (const float*)d_in[0];
    const float* w_ih = (const float*)d_in[1];
    const float* w_hh = (const float*)d_in[2];
    const float* b_ih = (const float*)d_in[3];
    const float* b_hh = (const float*)d_in[4];

    float* out = (float*)d_out;
    float* hn  = out + (size_t)Bsz * Tlen * Hdim;
    float* cn  = hn + (size_t)Bsz * Hdim;

    static const size_t GEMM_SMEM = 4 * TILE_W * sizeof(uint32_t);   // 73728 B
    static const size_t SCAN_SMEM = SMEM_WORDS * sizeof(uint32_t);
    cudaFuncSetAttribute(gemm_pre, cudaFuncAttributeMaxDynamicSharedMemorySize,
                         (int)GEMM_SMEM);
    cudaFuncSetAttribute(lstm_scan, cudaFuncAttributeMaxDynamicSharedMemorySize,
                         (int)SCAN_SMEM);

    prep_kernel<<<(Bsz * Tlen * Idim) / 256, 256>>>(x, w_ih, w_hh);
    gemm_pre<<<dim3(G4H / 128, (Bsz * Tlen) / 128), 256, GEMM_SMEM>>>(b_ih, b_hh);
    lstm_scan<<<NBLK, 256, SCAN_SMEM>>>(out, hn, cn);
}